// round 11
// baseline (speedup 1.0000x reference)
#include <cuda_runtime.h>
#include <cstdint>

#define Bc   16
#define NFc  16
#define Nc   1024
#define Dc   128
#define Sc   8
#define Hc   128
#define BSc  (Bc*Sc)          // 128
#define NCHUNK 16
#define CHTOK  64             // tokens per chunk
#define LNB    16             // extra x-blocks doing next-frame LN
#define SCALEc 0.08838834764831845f
#define EPSc   1e-8f

// ---------------- device scratch ----------------
__device__ float g_Xn[(size_t)Bc*NFc*Nc*Dc];  // 134 MB: pre-LN'd inputs
__device__ float g_qt[BSc*Dc];
__device__ float g_qb[BSc];
__device__ float g_slots[BSc*Dc];
__device__ float g_Yapart[NCHUNK*BSc*Dc];
__device__ float g_rspart[NCHUNK*BSc];
__device__ float g_WcT[Dc*3*Dc];      // (Wih @ Wv)^T : [e][j]
__device__ float g_bc[3*Dc];          // Wih @ bv
__device__ float g_WhhT[Dc*3*Dc];
__device__ float g_W1T[Dc*Hc];
__device__ float g_W2T[Hc*Dc];
__device__ float g_MT[Dc*Dc];         // MT[e][d] = (Wk^T Wq)[d][e]
__device__ float g_qtb[Dc];           // Wk^T bq
__device__ float g_qbv[Dc];           // Wq^T bk
__device__ float g_qbb[1];            // bq . bk

// ---------------- helpers ----------------
__device__ __forceinline__ float sigmoidf_(float x) { return 1.0f / (1.0f + expf(-x)); }

__device__ __forceinline__ float bsum256(float v, float* red) {
    #pragma unroll
    for (int o = 16; o; o >>= 1) v += __shfl_xor_sync(0xffffffffu, v, o);
    int t = threadIdx.x;
    if ((t & 31) == 0) red[t >> 5] = v;
    __syncthreads();
    float r = red[0] + red[1] + red[2] + red[3] + red[4] + red[5] + red[6] + red[7];
    __syncthreads();
    return r;
}

__device__ __forceinline__ float rowsum2(float v, float red[2][4]) {
    int t = threadIdx.x;
    int lane = t & 31, wid = t >> 5;
    #pragma unroll
    for (int o = 16; o; o >>= 1) v += __shfl_xor_sync(0xffffffffu, v, o);
    if (t < 256 && lane == 0) red[wid >> 2][wid & 3] = v;
    __syncthreads();
    float s = 0.0f;
    if (t < 256) {
        int r = t >> 7;
        s = red[r][0] + red[r][1] + red[r][2] + red[r][3];
    }
    __syncthreads();
    return s;
}

// LN 64 rows of x -> g_Xn (warp-per-row-group), 256 threads
__device__ __forceinline__ void ln_rows64(const float* __restrict__ xg, float* __restrict__ dst,
                                          const float* __restrict__ g_in,
                                          const float* __restrict__ be_in) {
    const int t = threadIdx.x;
    const int lane = t & 31, w = t >> 5;
    float4 gg = ((const float4*)g_in)[lane];
    float4 bb = ((const float4*)be_in)[lane];
    #pragma unroll
    for (int r = w; r < 64; r += 8) {
        float4 v = ((const float4*)(xg + r * Dc))[lane];
        float s = v.x + v.y + v.z + v.w;
        #pragma unroll
        for (int o = 16; o; o >>= 1) s += __shfl_xor_sync(0xffffffffu, s, o);
        float m = s * (1.0f / 128.0f);
        float d0 = v.x - m, d1 = v.y - m, d2 = v.z - m, d3 = v.w - m;
        float ss = d0*d0 + d1*d1 + d2*d2 + d3*d3;
        #pragma unroll
        for (int o = 16; o; o >>= 1) ss += __shfl_xor_sync(0xffffffffu, ss, o);
        float inv = rsqrtf(ss * (1.0f / 128.0f) + 1e-5f);
        float4 o4 = make_float4(d0 * inv * gg.x + bb.x, d1 * inv * gg.y + bb.y,
                                d2 * inv * gg.z + bb.z, d3 * inv * gg.w + bb.w);
        ((float4*)(dst + r * Dc))[lane] = o4;
    }
}

// ---------------- prepT: transposes + bias vectors ----------------
__global__ void prepT_kernel(const float* __restrict__ Wq, const float* __restrict__ bq,
                             const float* __restrict__ Wk, const float* __restrict__ bk,
                             const float* __restrict__ W1, const float* __restrict__ W2,
                             const float* __restrict__ Wih, const float* __restrict__ Whh,
                             const float* __restrict__ bv) {
    int blk = blockIdx.x;
    int t = threadIdx.x;
    if (blk < 192) {
        int idx = blk * 256 + t;
        int j = idx >> 7, d = idx & 127;
        g_WhhT[d * 384 + j] = Whh[idx];
        if (idx < Dc * Dc) {
            int r = idx >> 7, c = idx & 127;
            g_W1T[c * Dc + r] = W1[idx];
            g_W2T[c * Dc + r] = W2[idx];
        }
    } else {
        if (t < 128) {
            float aq = 0.0f, ab = 0.0f;
            for (int j = 0; j < 128; j++) {
                aq += Wq[j * 128 + t] * bk[j];
                ab += Wk[j * 128 + t] * bq[j];
            }
            g_qbv[t] = aq;
            g_qtb[t] = ab;
            if (t == 0) {
                float s = 0.0f;
                for (int j = 0; j < 128; j++) s += bq[j] * bk[j];
                g_qbb[0] = s;
            }
        }
        for (int j = t; j < 384; j += 256) {
            float s = 0.0f;
            for (int d = 0; d < 128; d++) s += Wih[j * 128 + d] * bv[d];
            g_bc[j] = s;
        }
    }
}

// ---------------- prepM: Wc (blk<384) and MT (blk>=384) -----------------
__global__ void prepM_kernel(const float* __restrict__ Wih, const float* __restrict__ Wv,
                             const float* __restrict__ Wq, const float* __restrict__ Wk) {
    __shared__ float row[128];
    int blk = blockIdx.x;
    if (blk < 384) {
        int j = blk, e = threadIdx.x;
        row[e] = Wih[j * 128 + e];
        __syncthreads();
        float s = 0.0f;
        #pragma unroll 8
        for (int d = 0; d < 128; d++) s += row[d] * Wv[d * 128 + e];
        g_WcT[e * 384 + j] = s;
    } else {
        int e = blk - 384, d = threadIdx.x;
        float s = 0.0f;
        #pragma unroll 8
        for (int j = 0; j < 128; j++) s += Wk[j * 128 + d] * Wq[j * 128 + e];
        g_MT[e * 128 + d] = s;
    }
}

// ---------------- ln0: LN frame 0 into g_Xn -----------------------------
// grid (16 xblk, 16 b), 256 threads
__global__ void ln0_kernel(const float* __restrict__ x,
                           const float* __restrict__ g_in, const float* __restrict__ be_in) {
    const int xb = blockIdx.x, b = blockIdx.y;
    const size_t base = ((size_t)(b * NFc + 0) * Nc + (size_t)xb * 64) * Dc;
    ln_rows64(x + base, g_Xn + base, g_in, be_in);
}

// ---------------- init: slots broadcast + first qt/qb -------------------
__global__ void init_kernel(const float* __restrict__ slots_init,
                            const float* __restrict__ g_sl, const float* __restrict__ be_sl) {
    __shared__ float lnv[Dc];
    __shared__ float part[2][Dc];
    __shared__ float red[8];
    const int t = threadIdx.x;
    const int bs = blockIdx.x;
    const int s = bs & 7;
    float v = 0.0f;
    if (t < 128) {
        v = slots_init[s * Dc + t];
        g_slots[bs * Dc + t] = v;
    }
    float m = bsum256(v, red) * (1.0f / 128.0f);
    float dx = (t < 128) ? (v - m) : 0.0f;
    float var = bsum256(dx * dx, red) * (1.0f / 128.0f);
    if (t < 128) lnv[t] = dx * rsqrtf(var + 1e-5f) * g_sl[t] + be_sl[t];
    __syncthreads();
    {
        int col = t & 127, h2 = t >> 7;
        float acc = 0.0f;
        #pragma unroll 8
        for (int i = 0; i < 64; i++) {
            int e = h2 * 64 + i;
            acc += g_MT[e * 128 + col] * lnv[e];
        }
        part[h2][col] = acc;
    }
    __syncthreads();
    if (t < 128) g_qt[bs * Dc + t] = part[0][t] + part[1][t] + g_qtb[t];
    float qv = (t < 128) ? (g_qbv[t] * lnv[t]) : 0.0f;
    float qb = bsum256(qv, red);
    if (t == 0) g_qb[bs] = qb + g_qbb[0];
}

// ---------------- stepB: dots/softmax/ya (x<16) + next-frame LN (x>=16) --
// grid (NCHUNK+LNB, Bc), 256 threads
#define XST 132
#define ASTB 65
__global__ void __launch_bounds__(256) stepB_kernel(
        const float* __restrict__ x, int f, int lnf, int emit, float* __restrict__ out_attn,
        const float* __restrict__ g_in, const float* __restrict__ be_in) {
    __shared__ float xs[CHTOK * XST];
    __shared__ float qts[Sc * XST];
    __shared__ float as[Sc * ASTB];
    __shared__ float qbs[Sc];

    const int t = threadIdx.x;
    const int lane = t & 31, w = t >> 5;
    const int b = blockIdx.y;

    if (blockIdx.x >= NCHUNK) {
        // LN duty: frame lnf, 64 rows per block
        if (lnf >= 0) {
            const int xb = blockIdx.x - NCHUNK;
            const size_t base = ((size_t)(b * NFc + lnf) * Nc + (size_t)xb * 64) * Dc;
            ln_rows64(x + base, g_Xn + base, g_in, be_in);
        }
        return;
    }

    const int chunk = blockIdx.x;
    const int bf = b * NFc + f;
    const float* xg = g_Xn + ((size_t)bf * Nc + (size_t)chunk * CHTOK) * Dc;

    // stage pre-LN'd x: 64 rows x 32 quads; 8 float4 per thread
    #pragma unroll
    for (int i = 0; i < 8; i++) {
        int l = t + i * 256;
        int r = l >> 5, dq = (l & 31) * 4;
        *(float4*)(xs + r * XST + dq) = *(const float4*)(xg + r * Dc + dq);
    }
    {
        int s = t >> 5, dq = (t & 31) * 4;
        *(float4*)(qts + s * XST + dq) = *(const float4*)(g_qt + (b * Sc + s) * Dc + dq);
    }
    if (t < 8) qbs[t] = g_qb[b * Sc + t];
    __syncthreads();

    // dots for tokens tt0, tt0+32, slot s
    const int tt0 = t >> 3;
    const int s = t & 7;
    float dot0 = 0.0f, dot1 = 0.0f;
    const float* qrow = qts + s * XST;
    const float* xrow0 = xs + tt0 * XST;
    const float* xrow1 = xrow0 + 32 * XST;
    #pragma unroll 8
    for (int j = 0; j < 32; j++) {
        float4 q4 = *(const float4*)(qrow + j * 4);
        float4 x0 = *(const float4*)(xrow0 + j * 4);
        float4 x1 = *(const float4*)(xrow1 + j * 4);
        dot0 += q4.x*x0.x + q4.y*x0.y + q4.z*x0.z + q4.w*x0.w;
        dot1 += q4.x*x1.x + q4.y*x1.y + q4.z*x1.z + q4.w*x1.w;
    }
    float qbv = qbs[s];
    dot0 = (dot0 + qbv) * SCALEc;
    dot1 = (dot1 + qbv) * SCALEc;
    float mx0 = dot0, mx1 = dot1;
    #pragma unroll
    for (int o = 4; o; o >>= 1) {
        mx0 = fmaxf(mx0, __shfl_xor_sync(0xffffffffu, mx0, o));
        mx1 = fmaxf(mx1, __shfl_xor_sync(0xffffffffu, mx1, o));
    }
    float e0 = expf(dot0 - mx0), e1 = expf(dot1 - mx1);
    float s0 = e0, s1 = e1;
    #pragma unroll
    for (int o = 4; o; o >>= 1) {
        s0 += __shfl_xor_sync(0xffffffffu, s0, o);
        s1 += __shfl_xor_sync(0xffffffffu, s1, o);
    }
    float a0 = e0 / s0 + EPSc;
    float a1 = e1 / s1 + EPSc;
    as[s * ASTB + tt0] = a0;
    as[s * ASTB + tt0 + 32] = a1;
    __syncthreads();

    if (emit) {
        float* oa = out_attn + (size_t)bf * Sc * Nc + chunk * CHTOK;
        #pragma unroll
        for (int i = 0; i < 2; i++) {
            int idx = t + i * 256;
            int s3 = idx >> 6, n3 = idx & 63;
            oa[(size_t)s3 * Nc + n3] = as[s3 * ASTB + n3];
        }
    }

    // rowsum partials: warp w -> slot w
    {
        float rs = as[w * ASTB + lane] + as[w * ASTB + lane + 32];
        #pragma unroll
        for (int o = 16; o; o >>= 1) rs += __shfl_xor_sync(0xffffffffu, rs, o);
        if (lane == 0) g_rspart[chunk * BSc + b * Sc + w] = rs;
    }

    // ya partials: warp w = slot w; lane owns d-quad
    {
        float4 up = make_float4(0.f, 0.f, 0.f, 0.f);
        const float* arow = as + w * ASTB;
        #pragma unroll 8
        for (int n = 0; n < CHTOK; n++) {
            float a = arow[n];
            float4 v4 = *(const float4*)(xs + n * XST + lane * 4);
            up.x += a * v4.x; up.y += a * v4.y;
            up.z += a * v4.z; up.w += a * v4.w;
        }
        *(float4*)(g_Yapart + (size_t)(chunk * BSc + b * Sc + w) * Dc + lane * 4) = up;
    }
}

// ---------------- stepC: 2 slot-rows per block (R10) --------------------
__global__ void __launch_bounds__(768) stepC_kernel(int f, int emit, float* __restrict__ out_slots,
                             const float* __restrict__ bih, const float* __restrict__ bhh,
                             const float* __restrict__ g_ff, const float* __restrict__ be_ff,
                             const float* __restrict__ b1, const float* __restrict__ b2,
                             const float* __restrict__ g_sl, const float* __restrict__ be_sl) {
    __shared__ float yn[2][Dc], hs[2][Dc], hgs[2][Dc], ffs[2][Dc], hid[2][Dc], ln2[2][Dc];
    __shared__ float gi[2][384], gh[2][384];
    __shared__ float part[4][2][Dc];
    __shared__ float rsp[2][NCHUNK];
    __shared__ float red[2][4];

    const int t = threadIdx.x;
    const int bs0 = blockIdx.x * 2;

    if (t < 32) {
        int r = t >> 4, c = t & 15;
        rsp[r][c] = g_rspart[c * BSc + bs0 + r];
    }
    if (t < 256) {
        int r = t >> 7, d = t & 127;
        hs[r][d] = g_slots[(bs0 + r) * Dc + d];
    }
    __syncthreads();
    if (t < 256) {
        int r = t >> 7, d = t & 127;
        float ysum = 0.0f;
        #pragma unroll 8
        for (int c = 0; c < NCHUNK; c++) ysum += g_Yapart[(size_t)(c * BSc + bs0 + r) * Dc + d];
        float rsum = 0.0f;
        #pragma unroll
        for (int c = 0; c < NCHUNK; c++) rsum += rsp[r][c];
        yn[r][d] = ysum / rsum;
    }
    __syncthreads();

    // gate GEMVs, 2-row reuse
    {
        int j = (t < 384) ? t : t - 384;
        const float* W = (t < 384) ? g_WcT : g_WhhT;
        const float* src = (t < 384) ? &yn[0][0] : &hs[0][0];
        float a0 = 0.f, a1 = 0.f;
        #pragma unroll 16
        for (int e = 0; e < 128; e++) {
            float wv = W[e * 384 + j];
            a0 += wv * src[e];
            a1 += wv * src[Dc + e];
        }
        float* dst = (t < 384) ? &gi[0][0] : &gh[0][0];
        dst[j] = a0;
        dst[384 + j] = a1;
    }
    __syncthreads();

    float hg = 0.0f;
    if (t < 256) {
        int r = t >> 7, d = t & 127;
        float gi_r = gi[r][d]       + g_bc[d]       + bih[d];
        float gh_r = gh[r][d]       + bhh[d];
        float gi_z = gi[r][128 + d] + g_bc[128 + d] + bih[128 + d];
        float gh_z = gh[r][128 + d] + bhh[128 + d];
        float gi_n = gi[r][256 + d] + g_bc[256 + d] + bih[256 + d];
        float gh_n = gh[r][256 + d] + bhh[256 + d];
        float rr = sigmoidf_(gi_r + gh_r);
        float z  = sigmoidf_(gi_z + gh_z);
        float nn = tanhf(gi_n + rr * gh_n);
        hg = (1.0f - z) * nn + z * hs[r][d];
        hgs[r][d] = hg;
    }
    {
        float v = (t < 256) ? hg : 0.0f;
        float m = rowsum2(v, red) * (1.0f / 128.0f);
        float dx = (t < 256) ? (hg - m) : 0.0f;
        float var = rowsum2(dx * dx, red) * (1.0f / 128.0f);
        if (t < 256) {
            int r = t >> 7, d = t & 127;
            ffs[r][d] = dx * rsqrtf(var + 1e-5f) * g_ff[d] + be_ff[d];
        }
    }
    __syncthreads();

    if (t < 512) {
        int col = t & 127, h4 = t >> 7;
        float a0 = 0.f, a1 = 0.f;
        #pragma unroll 8
        for (int i = 0; i < 32; i++) {
            int d = h4 * 32 + i;
            float wv = g_W1T[d * Dc + col];
            a0 += wv * ffs[0][d];
            a1 += wv * ffs[1][d];
        }
        part[h4][0][col] = a0;
        part[h4][1][col] = a1;
    }
    __syncthreads();
    if (t < 256) {
        int r = t >> 7, d = t & 127;
        hid[r][d] = fmaxf(part[0][r][d] + part[1][r][d] + part[2][r][d] + part[3][r][d] + b1[d], 0.0f);
    }
    __syncthreads();

    if (t < 512) {
        int col = t & 127, h4 = t >> 7;
        float a0 = 0.f, a1 = 0.f;
        #pragma unroll 8
        for (int i = 0; i < 32; i++) {
            int d = h4 * 32 + i;
            float wv = g_W2T[d * Dc + col];
            a0 += wv * hid[0][d];
            a1 += wv * hid[1][d];
        }
        part[h4][0][col] = a0;
        part[h4][1][col] = a1;
    }
    __syncthreads();
    float snew = 0.0f;
    if (t < 256) {
        int r = t >> 7, d = t & 127;
        snew = hgs[r][d] + part[0][r][d] + part[1][r][d] + part[2][r][d] + part[3][r][d] + b2[d];
        g_slots[(bs0 + r) * Dc + d] = snew;
        if (emit) {
            int bs = bs0 + r;
            int b = bs >> 3, s = bs & 7;
            out_slots[(((size_t)b * NFc + f) * Sc + s) * Dc + d] = snew;
        }
    }

    {
        float v = (t < 256) ? snew : 0.0f;
        float m = rowsum2(v, red) * (1.0f / 128.0f);
        float dx = (t < 256) ? (snew - m) : 0.0f;
        float var = rowsum2(dx * dx, red) * (1.0f / 128.0f);
        if (t < 256) {
            int r = t >> 7, d = t & 127;
            ln2[r][d] = dx * rsqrtf(var + 1e-5f) * g_sl[d] + be_sl[d];
        }
    }
    __syncthreads();
    {
        float qv = 0.0f;
        if (t < 256) {
            int r = t >> 7, d = t & 127;
            qv = g_qbv[d] * ln2[r][d];
        }
        float qb = rowsum2(qv, red);
        if (t < 256 && (t & 127) == 0) g_qb[bs0 + (t >> 7)] = qb + g_qbb[0];
    }
    if (t < 512) {
        int col = t & 127, h4 = t >> 7;
        float a0 = 0.f, a1 = 0.f;
        #pragma unroll 8
        for (int i = 0; i < 32; i++) {
            int e = h4 * 32 + i;
            float wv = g_MT[e * 128 + col];
            a0 += wv * ln2[0][e];
            a1 += wv * ln2[1][e];
        }
        part[h4][0][col] = a0;
        part[h4][1][col] = a1;
    }
    __syncthreads();
    if (t < 256) {
        int r = t >> 7, d = t & 127;
        g_qt[(bs0 + r) * Dc + d] = part[0][r][d] + part[1][r][d] + part[2][r][d] + part[3][r][d] + g_qtb[d];
    }
}

// ---------------- launch ----------------
extern "C" void kernel_launch(void* const* d_in, const int* in_sizes, int n_in,
                              void* d_out, int out_size) {
    const float* inputs     = (const float*)d_in[0];
    const float* slots_init = (const float*)d_in[1];
    const float* Wq  = (const float*)d_in[2];
    const float* bq  = (const float*)d_in[3];
    const float* Wk  = (const float*)d_in[4];
    const float* bk  = (const float*)d_in[5];
    const float* Wv  = (const float*)d_in[6];
    const float* bv  = (const float*)d_in[7];
    const float* W1  = (const float*)d_in[8];
    const float* b1  = (const float*)d_in[9];
    const float* W2  = (const float*)d_in[10];
    const float* b2  = (const float*)d_in[11];
    const float* Wih = (const float*)d_in[12];
    const float* Whh = (const float*)d_in[13];
    const float* bih = (const float*)d_in[14];
    const float* bhh = (const float*)d_in[15];
    const float* g_in  = (const float*)d_in[16];
    const float* be_in = (const float*)d_in[17];
    const float* g_sl  = (const float*)d_in[18];
    const float* be_sl = (const float*)d_in[19];
    const float* g_ff  = (const float*)d_in[20];
    const float* be_ff = (const float*)d_in[21];

    float* out = (float*)d_out;
    float* out_slots = out;                                 // [B,NF,S,D]
    float* out_attn  = out + (size_t)Bc * NFc * Sc * Dc;    // [B,NF,S,N]

    prepT_kernel<<<193, 256>>>(Wq, bq, Wk, bk, W1, W2, Wih, Whh, bv);
    prepM_kernel<<<512, 128>>>(Wih, Wv, Wq, Wk);
    ln0_kernel<<<dim3(16, Bc), 256>>>(inputs, g_in, be_in);
    init_kernel<<<BSc, 256>>>(slots_init, g_sl, be_sl);

    for (int step = 0; step < NFc + 1; step++) {
        int f = (step == 0) ? 0 : step - 1;
        int emit = (step > 0) ? 1 : 0;
        int lnf = (step >= 1 && step <= 15) ? step : -1;   // prepare frame for step+1
        stepB_kernel<<<dim3(NCHUNK + LNB, Bc), 256>>>(inputs, f, lnf, emit, out_attn, g_in, be_in);
        stepC_kernel<<<64, 768>>>(f, emit, out_slots,
                                  bih, bhh, g_ff, be_ff, b1, b2, g_sl, be_sl);
    }
}

// round 12
// speedup vs baseline: 1.0726x; 1.0726x over previous
#include <cuda_runtime.h>
#include <cstdint>

#define Bc   16
#define NFc  16
#define Nc   1024
#define Dc   128
#define Sc   8
#define Hc   128
#define BSc  (Bc*Sc)          // 128
#define NCHUNK 32
#define CHTOK  32             // tokens per chunk
#define SCALEc 0.08838834764831845f
#define EPSc   1e-8f

// ---------------- device scratch ----------------
__device__ float g_qt[BSc*Dc];
__device__ float g_qb[BSc];
__device__ float g_slots[BSc*Dc];
__device__ float g_Yapart[NCHUNK*BSc*Dc];   // 2 MB
__device__ float g_rspart[NCHUNK*BSc];
__device__ float g_WcT[Dc*3*Dc];      // (Wih @ Wv)^T : [e][j]
__device__ float g_bc[3*Dc];          // Wih @ bv
__device__ float g_WhhT[Dc*3*Dc];
__device__ float g_W1T[Dc*Hc];
__device__ float g_W2T[Hc*Dc];
__device__ float g_MT[Dc*Dc];         // MT[e][d] = (Wk^T Wq)[d][e]
__device__ float g_qtb[Dc];           // Wk^T bq
__device__ float g_qbv[Dc];           // Wq^T bk
__device__ float g_qbb[1];            // bq . bk

// ---------------- helpers ----------------
__device__ __forceinline__ float sigmoidf_(float x) { return 1.0f / (1.0f + expf(-x)); }

__device__ __forceinline__ float bsum256(float v, float* red) {
    #pragma unroll
    for (int o = 16; o; o >>= 1) v += __shfl_xor_sync(0xffffffffu, v, o);
    int t = threadIdx.x;
    if ((t & 31) == 0) red[t >> 5] = v;
    __syncthreads();
    float r = red[0] + red[1] + red[2] + red[3] + red[4] + red[5] + red[6] + red[7];
    __syncthreads();
    return r;
}

__device__ __forceinline__ float rowsum2(float v, float red[2][4]) {
    int t = threadIdx.x;
    int lane = t & 31, wid = t >> 5;
    #pragma unroll
    for (int o = 16; o; o >>= 1) v += __shfl_xor_sync(0xffffffffu, v, o);
    if (t < 256 && lane == 0) red[wid >> 2][wid & 3] = v;
    __syncthreads();
    float s = 0.0f;
    if (t < 256) {
        int r = t >> 7;
        s = red[r][0] + red[r][1] + red[r][2] + red[r][3];
    }
    __syncthreads();
    return s;
}

// ---------------- prep: transposes, folded matrices, bias vectors -------
// grid 705 blocks: [0,192) transposes, [192,193) vectors, [193,577) Wc, [577,705) MT
__global__ void prep_kernel(const float* __restrict__ Wq, const float* __restrict__ bq,
                            const float* __restrict__ Wk, const float* __restrict__ bk,
                            const float* __restrict__ W1, const float* __restrict__ W2,
                            const float* __restrict__ Wih, const float* __restrict__ Whh,
                            const float* __restrict__ Wv, const float* __restrict__ bv) {
    int blk = blockIdx.x;
    int t = threadIdx.x;
    if (blk < 192) {
        int idx = blk * 256 + t;
        int j = idx >> 7, d = idx & 127;
        g_WhhT[d * 384 + j] = Whh[idx];
        if (idx < Dc * Dc) {
            int r = idx >> 7, c = idx & 127;
            g_W1T[c * Dc + r] = W1[idx];
            g_W2T[c * Dc + r] = W2[idx];
        }
    } else if (blk == 192) {
        if (t < 128) {
            float aq = 0.0f, ab = 0.0f;
            for (int j = 0; j < 128; j++) {
                aq += Wq[j * 128 + t] * bk[j];
                ab += Wk[j * 128 + t] * bq[j];
            }
            g_qbv[t] = aq;
            g_qtb[t] = ab;
            if (t == 0) {
                float s = 0.0f;
                for (int j = 0; j < 128; j++) s += bq[j] * bk[j];
                g_qbb[0] = s;
            }
        }
        for (int j = t; j < 384; j += 256) {
            float s = 0.0f;
            for (int d = 0; d < 128; d++) s += Wih[j * 128 + d] * bv[d];
            g_bc[j] = s;
        }
    } else if (blk < 577) {
        __shared__ float row[128];
        int j = blk - 193;
        if (t < 128) row[t] = Wih[j * 128 + t];
        __syncthreads();
        if (t < 128) {
            int e = t;
            float s = 0.0f;
            #pragma unroll 8
            for (int d = 0; d < 128; d++) s += row[d] * Wv[d * 128 + e];
            g_WcT[e * 384 + j] = s;
        }
    } else {
        int e = blk - 577;
        if (t < 128) {
            int d = t;
            float s = 0.0f;
            #pragma unroll 8
            for (int j = 0; j < 128; j++) s += Wk[j * 128 + d] * Wq[j * 128 + e];
            g_MT[e * 128 + d] = s;
        }
    }
}

// ---------------- init: slots broadcast + first qt/qb -------------------
__global__ void init_kernel(const float* __restrict__ slots_init,
                            const float* __restrict__ g_sl, const float* __restrict__ be_sl) {
    __shared__ float lnv[Dc];
    __shared__ float part[2][Dc];
    __shared__ float red[8];
    const int t = threadIdx.x;
    const int bs = blockIdx.x;
    const int s = bs & 7;
    float v = 0.0f;
    if (t < 128) {
        v = slots_init[s * Dc + t];
        g_slots[bs * Dc + t] = v;
    }
    float m = bsum256(v, red) * (1.0f / 128.0f);
    float dx = (t < 128) ? (v - m) : 0.0f;
    float var = bsum256(dx * dx, red) * (1.0f / 128.0f);
    if (t < 128) lnv[t] = dx * rsqrtf(var + 1e-5f) * g_sl[t] + be_sl[t];
    __syncthreads();
    {
        int col = t & 127, h2 = t >> 7;
        float acc = 0.0f;
        #pragma unroll 8
        for (int i = 0; i < 64; i++) {
            int e = h2 * 64 + i;
            acc += g_MT[e * 128 + col] * lnv[e];
        }
        part[h2][col] = acc;
    }
    __syncthreads();
    if (t < 128) g_qt[bs * Dc + t] = part[0][t] + part[1][t] + g_qtb[t];
    float qv = (t < 128) ? (g_qbv[t] * lnv[t]) : 0.0f;
    float qb = bsum256(qv, red);
    if (t == 0) g_qb[bs] = qb + g_qbb[0];
}

// ---------------- stepB: LN(x), dots, softmax, ya/ra partials -----------
// grid (32 chunks of 32 tokens, 16 batches) = 512 blocks, 256 threads
#define XST 132
#define ASTB 33
__global__ void __launch_bounds__(256) stepB_kernel(
        const float* __restrict__ x, int f, int emit, float* __restrict__ out_attn,
        const float* __restrict__ g_in, const float* __restrict__ be_in) {
    __shared__ float xs[CHTOK * XST];
    __shared__ float qts[Sc * XST];
    __shared__ float as[Sc * ASTB];
    __shared__ float qbs[Sc];

    const int t = threadIdx.x;
    const int lane = t & 31, w = t >> 5;
    const int chunk = blockIdx.x;
    const int b = blockIdx.y;
    const int bf = b * NFc + f;
    const float* xg = x + ((size_t)bf * Nc + (size_t)chunk * CHTOK) * Dc;

    float4 gg = ((const float4*)g_in)[lane];
    float4 bb = ((const float4*)be_in)[lane];
    // LN: warp w handles rows w, w+8, w+16, w+24
    #pragma unroll
    for (int r = w; r < CHTOK; r += 8) {
        float4 v = ((const float4*)(xg + r * Dc))[lane];
        float s = v.x + v.y + v.z + v.w;
        #pragma unroll
        for (int o = 16; o; o >>= 1) s += __shfl_xor_sync(0xffffffffu, s, o);
        float m = s * (1.0f / 128.0f);
        float d0 = v.x - m, d1 = v.y - m, d2 = v.z - m, d3 = v.w - m;
        float ss = d0*d0 + d1*d1 + d2*d2 + d3*d3;
        #pragma unroll
        for (int o = 16; o; o >>= 1) ss += __shfl_xor_sync(0xffffffffu, ss, o);
        float inv = rsqrtf(ss * (1.0f / 128.0f) + 1e-5f);
        float* xr = xs + r * XST + lane * 4;
        xr[0] = d0 * inv * gg.x + bb.x;
        xr[1] = d1 * inv * gg.y + bb.y;
        xr[2] = d2 * inv * gg.z + bb.z;
        xr[3] = d3 * inv * gg.w + bb.w;
    }
    {
        int s = t >> 5, dq = (t & 31) * 4;
        *(float4*)(qts + s * XST + dq) = *(const float4*)(g_qt + (b * Sc + s) * Dc + dq);
    }
    if (t < 8) qbs[t] = g_qb[b * Sc + t];
    __syncthreads();

    // dots: thread -> (token tt, slot s)
    const int tt = t >> 3;
    const int s = t & 7;
    float dot = 0.0f;
    const float* qrow = qts + s * XST;
    const float* xrow = xs + tt * XST;
    #pragma unroll 8
    for (int j = 0; j < 32; j++) {
        float4 q4 = *(const float4*)(qrow + j * 4);
        float4 x4 = *(const float4*)(xrow + j * 4);
        dot += q4.x*x4.x + q4.y*x4.y + q4.z*x4.z + q4.w*x4.w;
    }
    dot = (dot + qbs[s]) * SCALEc;
    float mx = dot;
    #pragma unroll
    for (int o = 4; o; o >>= 1) mx = fmaxf(mx, __shfl_xor_sync(0xffffffffu, mx, o));
    float e = expf(dot - mx);
    float es = e;
    #pragma unroll
    for (int o = 4; o; o >>= 1) es += __shfl_xor_sync(0xffffffffu, es, o);
    float a = e / es + EPSc;
    as[s * ASTB + tt] = a;
    __syncthreads();

    // coalesced attn emit (8 slots x 32 tokens)
    if (emit) {
        int s3 = t >> 5, n3 = t & 31;
        out_attn[(size_t)bf * Sc * Nc + (size_t)s3 * Nc + chunk * CHTOK + n3] = as[s3 * ASTB + n3];
    }

    // rowsum: warp w -> slot w
    {
        float rs = as[w * ASTB + lane];
        #pragma unroll
        for (int o = 16; o; o >>= 1) rs += __shfl_xor_sync(0xffffffffu, rs, o);
        if (lane == 0) g_rspart[chunk * BSc + b * Sc + w] = rs;
    }

    // ya partials: warp w -> slot w; lane owns d-quad
    {
        float4 up = make_float4(0.f, 0.f, 0.f, 0.f);
        const float* arow = as + w * ASTB;
        #pragma unroll 8
        for (int n = 0; n < CHTOK; n++) {
            float a2 = arow[n];
            float4 v4 = *(const float4*)(xs + n * XST + lane * 4);
            up.x += a2 * v4.x; up.y += a2 * v4.y;
            up.z += a2 * v4.z; up.w += a2 * v4.w;
        }
        *(float4*)(g_Yapart + (size_t)(chunk * BSc + b * Sc + w) * Dc + lane * 4) = up;
    }
}

// ---------------- stepC: 2 slot-rows per block --------------------------
// grid 64 blocks, 768 threads
__global__ void __launch_bounds__(768) stepC_kernel(int f, int emit, float* __restrict__ out_slots,
                             const float* __restrict__ bih, const float* __restrict__ bhh,
                             const float* __restrict__ g_ff, const float* __restrict__ be_ff,
                             const float* __restrict__ b1, const float* __restrict__ b2,
                             const float* __restrict__ g_sl, const float* __restrict__ be_sl) {
    __shared__ float yn[2][Dc], hs[2][Dc], hgs[2][Dc], ffs[2][Dc], hid[2][Dc], ln2[2][Dc];
    __shared__ float gi[2][384], gh[2][384];
    __shared__ float part[4][2][Dc];
    __shared__ float rsp[2][NCHUNK];
    __shared__ float red[2][4];

    const int t = threadIdx.x;
    const int bs0 = blockIdx.x * 2;

    if (t < 64) {
        int r = t >> 5, c = t & 31;
        rsp[r][c] = g_rspart[c * BSc + bs0 + r];
    }
    if (t < 256) {
        int r = t >> 7, d = t & 127;
        hs[r][d] = g_slots[(bs0 + r) * Dc + d];
    }
    __syncthreads();
    if (t < 256) {
        int r = t >> 7, d = t & 127;
        float ysum = 0.0f;
        #pragma unroll 8
        for (int c = 0; c < NCHUNK; c++) ysum += g_Yapart[(size_t)(c * BSc + bs0 + r) * Dc + d];
        float rsum = 0.0f;
        #pragma unroll
        for (int c = 0; c < NCHUNK; c++) rsum += rsp[r][c];
        yn[r][d] = ysum / rsum;
    }
    __syncthreads();

    // gate GEMVs, 2-row reuse
    {
        int j = (t < 384) ? t : t - 384;
        const float* W = (t < 384) ? g_WcT : g_WhhT;
        const float* src = (t < 384) ? &yn[0][0] : &hs[0][0];
        float a0 = 0.f, a1 = 0.f;
        #pragma unroll 16
        for (int e = 0; e < 128; e++) {
            float wv = W[e * 384 + j];
            a0 += wv * src[e];
            a1 += wv * src[Dc + e];
        }
        float* dst = (t < 384) ? &gi[0][0] : &gh[0][0];
        dst[j] = a0;
        dst[384 + j] = a1;
    }
    __syncthreads();

    float hg = 0.0f;
    if (t < 256) {
        int r = t >> 7, d = t & 127;
        float gi_r = gi[r][d]       + g_bc[d]       + bih[d];
        float gh_r = gh[r][d]       + bhh[d];
        float gi_z = gi[r][128 + d] + g_bc[128 + d] + bih[128 + d];
        float gh_z = gh[r][128 + d] + bhh[128 + d];
        float gi_n = gi[r][256 + d] + g_bc[256 + d] + bih[256 + d];
        float gh_n = gh[r][256 + d] + bhh[256 + d];
        float rr = sigmoidf_(gi_r + gh_r);
        float z  = sigmoidf_(gi_z + gh_z);
        float nn = tanhf(gi_n + rr * gh_n);
        hg = (1.0f - z) * nn + z * hs[r][d];
        hgs[r][d] = hg;
    }
    {
        float v = (t < 256) ? hg : 0.0f;
        float m = rowsum2(v, red) * (1.0f / 128.0f);
        float dx = (t < 256) ? (hg - m) : 0.0f;
        float var = rowsum2(dx * dx, red) * (1.0f / 128.0f);
        if (t < 256) {
            int r = t >> 7, d = t & 127;
            ffs[r][d] = dx * rsqrtf(var + 1e-5f) * g_ff[d] + be_ff[d];
        }
    }
    __syncthreads();

    if (t < 512) {
        int col = t & 127, h4 = t >> 7;
        float a0 = 0.f, a1 = 0.f;
        #pragma unroll 8
        for (int i = 0; i < 32; i++) {
            int d = h4 * 32 + i;
            float wv = g_W1T[d * Dc + col];
            a0 += wv * ffs[0][d];
            a1 += wv * ffs[1][d];
        }
        part[h4][0][col] = a0;
        part[h4][1][col] = a1;
    }
    __syncthreads();
    if (t < 256) {
        int r = t >> 7, d = t & 127;
        hid[r][d] = fmaxf(part[0][r][d] + part[1][r][d] + part[2][r][d] + part[3][r][d] + b1[d], 0.0f);
    }
    __syncthreads();

    if (t < 512) {
        int col = t & 127, h4 = t >> 7;
        float a0 = 0.f, a1 = 0.f;
        #pragma unroll 8
        for (int i = 0; i < 32; i++) {
            int d = h4 * 32 + i;
            float wv = g_W2T[d * Dc + col];
            a0 += wv * hid[0][d];
            a1 += wv * hid[1][d];
        }
        part[h4][0][col] = a0;
        part[h4][1][col] = a1;
    }
    __syncthreads();
    float snew = 0.0f;
    if (t < 256) {
        int r = t >> 7, d = t & 127;
        snew = hgs[r][d] + part[0][r][d] + part[1][r][d] + part[2][r][d] + part[3][r][d] + b2[d];
        g_slots[(bs0 + r) * Dc + d] = snew;
        if (emit) {
            int bs = bs0 + r;
            int b = bs >> 3, s = bs & 7;
            out_slots[(((size_t)b * NFc + f) * Sc + s) * Dc + d] = snew;
        }
    }

    {
        float v = (t < 256) ? snew : 0.0f;
        float m = rowsum2(v, red) * (1.0f / 128.0f);
        float dx = (t < 256) ? (snew - m) : 0.0f;
        float var = rowsum2(dx * dx, red) * (1.0f / 128.0f);
        if (t < 256) {
            int r = t >> 7, d = t & 127;
            ln2[r][d] = dx * rsqrtf(var + 1e-5f) * g_sl[d] + be_sl[d];
        }
    }
    __syncthreads();
    {
        float qv = 0.0f;
        if (t < 256) {
            int r = t >> 7, d = t & 127;
            qv = g_qbv[d] * ln2[r][d];
        }
        float qb = rowsum2(qv, red);
        if (t < 256 && (t & 127) == 0) g_qb[bs0 + (t >> 7)] = qb + g_qbb[0];
    }
    if (t < 512) {
        int col = t & 127, h4 = t >> 7;
        float a0 = 0.f, a1 = 0.f;
        #pragma unroll 8
        for (int i = 0; i < 32; i++) {
            int e = h4 * 32 + i;
            float wv = g_MT[e * 128 + col];
            a0 += wv * ln2[0][e];
            a1 += wv * ln2[1][e];
        }
        part[h4][0][col] = a0;
        part[h4][1][col] = a1;
    }
    __syncthreads();
    if (t < 256) {
        int r = t >> 7, d = t & 127;
        g_qt[(bs0 + r) * Dc + d] = part[0][r][d] + part[1][r][d] + part[2][r][d] + part[3][r][d] + g_qtb[d];
    }
}

// ---------------- launch ----------------
extern "C" void kernel_launch(void* const* d_in, const int* in_sizes, int n_in,
                              void* d_out, int out_size) {
    const float* inputs     = (const float*)d_in[0];
    const float* slots_init = (const float*)d_in[1];
    const float* Wq  = (const float*)d_in[2];
    const float* bq  = (const float*)d_in[3];
    const float* Wk  = (const float*)d_in[4];
    const float* bk  = (const float*)d_in[5];
    const float* Wv  = (const float*)d_in[6];
    const float* bv  = (const float*)d_in[7];
    const float* W1  = (const float*)d_in[8];
    const float* b1  = (const float*)d_in[9];
    const float* W2  = (const float*)d_in[10];
    const float* b2  = (const float*)d_in[11];
    const float* Wih = (const float*)d_in[12];
    const float* Whh = (const float*)d_in[13];
    const float* bih = (const float*)d_in[14];
    const float* bhh = (const float*)d_in[15];
    const float* g_in  = (const float*)d_in[16];
    const float* be_in = (const float*)d_in[17];
    const float* g_sl  = (const float*)d_in[18];
    const float* be_sl = (const float*)d_in[19];
    const float* g_ff  = (const float*)d_in[20];
    const float* be_ff = (const float*)d_in[21];

    float* out = (float*)d_out;
    float* out_slots = out;                                 // [B,NF,S,D]
    float* out_attn  = out + (size_t)Bc * NFc * Sc * Dc;    // [B,NF,S,N]

    prep_kernel<<<705, 256>>>(Wq, bq, Wk, bk, W1, W2, Wih, Whh, Wv, bv);
    init_kernel<<<BSc, 256>>>(slots_init, g_sl, be_sl);

    for (int step = 0; step < NFc + 1; step++) {
        int f = (step == 0) ? 0 : step - 1;
        int emit = (step > 0) ? 1 : 0;
        stepB_kernel<<<dim3(NCHUNK, Bc), 256>>>(inputs, f, emit, out_attn, g_in, be_in);
        stepC_kernel<<<64, 768>>>(f, emit, out_slots,
                                  bih, bhh, g_ff, be_ff, b1, b2, g_sl, be_sl);
    }
}